// round 9
// baseline (speedup 1.0000x reference)
#include <cuda_runtime.h>
#include <cuda_bf16.h>

// LIF neuron forward over T=16 timesteps.
// x: [B=16, C=64, T=16, H=64, W=64] fp32, decay: [1] fp32.
// out[b,c,t,h,w] = spike_t where:
//   mem_t = mem_{t-1} * sigmoid(decay) * (1 - spike_{t-1}) + x_t
//   spike_t = (mem_t > 0.5) ? 1 : 0
//
// Pure HBM-streaming kernel at the ~6.3 TB/s chip floor. Confirmed-best
// config (R2/R7, reproduced 82.6/82.7us): 16-deep .cs load batch (the .cs
// is what stops ptxas from collapsing the batch; regs 80, occ 31%) followed
// by a 16-deep store burst. This round escalates the L2-protection
// mechanism: stores use __stwt (write-through, no-allocate) so the
// never-re-read 256 MB spike stream doesn't occupy L2 at all, leaving the
// full L2 to buffer the read stream.

#define T_STEPS 16
#define HW 4096                    // 64*64
#define BC 1024                    // 16*64
#define VEC4_PER_PLANE (HW / 4)    // 1024 float4 per (bc,t) plane

__global__ __launch_bounds__(256) void lif_kernel(
    const float* __restrict__ x,
    const float* __restrict__ decay,
    float* __restrict__ out)
{
    const float d  = decay[0];
    const float ds = 1.0f / (1.0f + __expf(-d));

    const unsigned g  = blockIdx.x * blockDim.x + threadIdx.x;
    const unsigned bc = g >> 10;        // which (b,c) slab
    const unsigned s4 = g & 1023u;      // which float4 within the HW plane

    const size_t base = (size_t)bc * (T_STEPS * HW) + (size_t)s4 * 4;

    const float4* __restrict__ xin  = (const float4*)(x + base);
    float4* __restrict__ xout = (float4*)(out + base);

    // ---- phase 1: batch all 16 independent streaming loads (MLP=16) ----
    float4 xv[T_STEPS];
#pragma unroll
    for (int t = 0; t < T_STEPS; t++) {
        xv[t] = __ldcs(&xin[(size_t)t * VEC4_PER_PLANE]);
    }

    // ---- phase 2: sequential recurrence + write-through store burst ----
    float4 mem = make_float4(0.f, 0.f, 0.f, 0.f);
    float4 spk = make_float4(0.f, 0.f, 0.f, 0.f);

#pragma unroll
    for (int t = 0; t < T_STEPS; t++) {
        mem.x = mem.x * ds * (1.0f - spk.x) + xv[t].x;
        mem.y = mem.y * ds * (1.0f - spk.y) + xv[t].y;
        mem.z = mem.z * ds * (1.0f - spk.z) + xv[t].z;
        mem.w = mem.w * ds * (1.0f - spk.w) + xv[t].w;

        spk.x = (mem.x > 0.5f) ? 1.0f : 0.0f;
        spk.y = (mem.y > 0.5f) ? 1.0f : 0.0f;
        spk.z = (mem.z > 0.5f) ? 1.0f : 0.0f;
        spk.w = (mem.w > 0.5f) ? 1.0f : 0.0f;

        __stwt(&xout[(size_t)t * VEC4_PER_PLANE], spk);
    }
}

extern "C" void kernel_launch(void* const* d_in, const int* in_sizes, int n_in,
                              void* d_out, int out_size)
{
    const float* x     = (const float*)d_in[0];
    const float* decay = (const float*)d_in[1];
    float* out = (float*)d_out;

    const int threads = 256;
    const int blocks  = (BC * VEC4_PER_PLANE) / threads;  // 4096
    lif_kernel<<<blocks, threads>>>(x, decay, out);
}

// round 10
// speedup vs baseline: 1.0268x; 1.0268x over previous
#include <cuda_runtime.h>
#include <cuda_bf16.h>

// LIF neuron forward over T=16 timesteps. FINAL KERNEL.
// x: [B=16, C=64, T=16, H=64, W=64] fp32, decay: [1] fp32.
// out[b,c,t,h,w] = spike_t where:
//   mem_t = mem_{t-1} * sigmoid(decay) * (1 - spike_{t-1}) + x_t
//   spike_t = (mem_t > 0.5) ? 1 : 0
// (output clip is identity since spike in {0,1})
//
// Pure HBM-streaming kernel: 512 MB irreducible traffic, zero reuse,
// running at ~90% of the B300's measured path-independent LTS chip cap.
// Session-converged configuration (reproduced twice at 82.6/82.7 us,
// vs 84.0-86.8 for all alternatives):
//   - 16-deep front-batched LDG.128.CS (the .cs is load-bearing: it both
//     marks the stream evict-first in L2 AND prevents ptxas from
//     collapsing the batch back into an interleaved schedule)
//   - sequential recurrence on registers
//   - 16-deep STG.128.CS write burst (evict-first, still write-allocating
//     so L2 coalesces sectors; .wt write-through measured as a regression)
//   - regs 80 / occ ~31%: occupancy is non-binding for this kernel
//     (in-flight bytes >> BW*latency requirement at every tested occ)
//   - plain 4096x256 grid (persistent grid measured as a regression)

#define T_STEPS 16
#define HW 4096                    // 64*64
#define BC 1024                    // 16*64
#define VEC4_PER_PLANE (HW / 4)    // 1024 float4 per (bc,t) plane

__global__ __launch_bounds__(256) void lif_kernel(
    const float* __restrict__ x,
    const float* __restrict__ decay,
    float* __restrict__ out)
{
    const float d  = decay[0];
    const float ds = 1.0f / (1.0f + __expf(-d));

    const unsigned g  = blockIdx.x * blockDim.x + threadIdx.x;
    const unsigned bc = g >> 10;        // which (b,c) slab
    const unsigned s4 = g & 1023u;      // which float4 within the HW plane

    const size_t base = (size_t)bc * (T_STEPS * HW) + (size_t)s4 * 4;

    const float4* __restrict__ xin  = (const float4*)(x + base);
    float4* __restrict__ xout = (float4*)(out + base);

    // ---- phase 1: batch all 16 independent streaming loads (MLP=16) ----
    float4 xv[T_STEPS];
#pragma unroll
    for (int t = 0; t < T_STEPS; t++) {
        xv[t] = __ldcs(&xin[(size_t)t * VEC4_PER_PLANE]);
    }

    // ---- phase 2: sequential recurrence + streaming store burst ----
    float4 mem = make_float4(0.f, 0.f, 0.f, 0.f);
    float4 spk = make_float4(0.f, 0.f, 0.f, 0.f);

#pragma unroll
    for (int t = 0; t < T_STEPS; t++) {
        mem.x = mem.x * ds * (1.0f - spk.x) + xv[t].x;
        mem.y = mem.y * ds * (1.0f - spk.y) + xv[t].y;
        mem.z = mem.z * ds * (1.0f - spk.z) + xv[t].z;
        mem.w = mem.w * ds * (1.0f - spk.w) + xv[t].w;

        spk.x = (mem.x > 0.5f) ? 1.0f : 0.0f;
        spk.y = (mem.y > 0.5f) ? 1.0f : 0.0f;
        spk.z = (mem.z > 0.5f) ? 1.0f : 0.0f;
        spk.w = (mem.w > 0.5f) ? 1.0f : 0.0f;

        __stcs(&xout[(size_t)t * VEC4_PER_PLANE], spk);
    }
}

extern "C" void kernel_launch(void* const* d_in, const int* in_sizes, int n_in,
                              void* d_out, int out_size)
{
    const float* x     = (const float*)d_in[0];
    const float* decay = (const float*)d_in[1];
    float* out = (float*)d_out;

    const int threads = 256;
    const int blocks  = (BC * VEC4_PER_PLANE) / threads;  // 4096
    lif_kernel<<<blocks, threads>>>(x, decay, out);
}

// round 11
// speedup vs baseline: 1.0316x; 1.0047x over previous
#include <cuda_runtime.h>
#include <cuda_bf16.h>

// LIF neuron forward over T=16 timesteps.
// x: [B=16, C=64, T=16, H=64, W=64] fp32, decay: [1] fp32.
// out[b,c,t,h,w] = spike_t where:
//   mem_t = mem_{t-1} * sigmoid(decay) * (1 - spike_{t-1}) + x_t
//   spike_t = (mem_t > 0.5) ? 1 : 0
//
// Pure HBM-streaming kernel (512 MB irreducible traffic). Converged config
// (3x reproduced at 82.4-82.7us): 16-deep front-batched LDG.128.CS, register
// recurrence, 16-deep STG.128.CS burst. This round probes the one untested
// orthogonal knob: CTA granularity 256 -> 128 threads (same 24 warps/SM,
// 6 CTAs/SM instead of 3) for finer tail-wave balance and per-CTA burst
// locality in the L1tex queue. Risk-free probe: record kernel stands if
// this is neutral.

#define T_STEPS 16
#define HW 4096                    // 64*64
#define BC 1024                    // 16*64
#define VEC4_PER_PLANE (HW / 4)    // 1024 float4 per (bc,t) plane
#define BLOCK 128

__global__ __launch_bounds__(BLOCK) void lif_kernel(
    const float* __restrict__ x,
    const float* __restrict__ decay,
    float* __restrict__ out)
{
    const float d  = decay[0];
    const float ds = 1.0f / (1.0f + __expf(-d));

    const unsigned g  = blockIdx.x * BLOCK + threadIdx.x;
    const unsigned bc = g >> 10;        // which (b,c) slab
    const unsigned s4 = g & 1023u;      // which float4 within the HW plane

    const size_t base = (size_t)bc * (T_STEPS * HW) + (size_t)s4 * 4;

    const float4* __restrict__ xin  = (const float4*)(x + base);
    float4* __restrict__ xout = (float4*)(out + base);

    // ---- phase 1: batch all 16 independent streaming loads (MLP=16) ----
    float4 xv[T_STEPS];
#pragma unroll
    for (int t = 0; t < T_STEPS; t++) {
        xv[t] = __ldcs(&xin[(size_t)t * VEC4_PER_PLANE]);
    }

    // ---- phase 2: sequential recurrence + streaming store burst ----
    float4 mem = make_float4(0.f, 0.f, 0.f, 0.f);
    float4 spk = make_float4(0.f, 0.f, 0.f, 0.f);

#pragma unroll
    for (int t = 0; t < T_STEPS; t++) {
        mem.x = mem.x * ds * (1.0f - spk.x) + xv[t].x;
        mem.y = mem.y * ds * (1.0f - spk.y) + xv[t].y;
        mem.z = mem.z * ds * (1.0f - spk.z) + xv[t].z;
        mem.w = mem.w * ds * (1.0f - spk.w) + xv[t].w;

        spk.x = (mem.x > 0.5f) ? 1.0f : 0.0f;
        spk.y = (mem.y > 0.5f) ? 1.0f : 0.0f;
        spk.z = (mem.z > 0.5f) ? 1.0f : 0.0f;
        spk.w = (mem.w > 0.5f) ? 1.0f : 0.0f;

        __stcs(&xout[(size_t)t * VEC4_PER_PLANE], spk);
    }
}

extern "C" void kernel_launch(void* const* d_in, const int* in_sizes, int n_in,
                              void* d_out, int out_size)
{
    const float* x     = (const float*)d_in[0];
    const float* decay = (const float*)d_in[1];
    float* out = (float*)d_out;

    const int blocks = (BC * VEC4_PER_PLANE) / BLOCK;  // 8192
    lif_kernel<<<blocks, BLOCK>>>(x, decay, out);
}